// round 4
// baseline (speedup 1.0000x reference)
#include <cuda_runtime.h>
#include <cuda_bf16.h>

// Problem constants (buffers statically sized; runtime sizes from in_sizes)
#define NMAX 50000
#define EMAX 800000

// -------- scratch (device globals; no allocations allowed) ----------
__device__ __align__(16) float g_xl1[NMAX * 64];
__device__ __align__(16) float g_xr1[NMAX * 64];
__device__ __align__(16) float g_agg1[NMAX * 64];
__device__ __align__(16) float g_xl2[NMAX * 32];
__device__ __align__(16) float g_xr2[NMAX * 32];
__device__ __align__(16) float g_agg2[NMAX * 32];
__device__ __align__(16) float g_expv[EMAX];
__device__ __align__(16) float g_den1[NMAX];
__device__ __align__(16) float g_den2[NMAX];

// -------- zero the accumulators ------------------------------------
__global__ void zero_kernel(int n) {
    int i = blockIdx.x * blockDim.x + threadIdx.x;
    int stride = gridDim.x * blockDim.x;
    for (int j = i; j < n * 64; j += stride) g_agg1[j] = 0.f;
    for (int j = i; j < n * 32; j += stride) g_agg2[j] = 0.f;
    for (int j = i; j < n; j += stride) { g_den1[j] = 0.f; g_den2[j] = 0.f; }
}

// -------- GEMM: out[n, COUT] = f(X)[n, CIN] @ W[CIN, COUT] ----------
// SRC: 0 = external X param, 1 = g_agg1.  DST: 0=g_xl1 1=g_xr1 2=g_xl2 3=g_xr2.
// f = identity, or relu(x + bin) when RELU_IN (layer-2 input transform).
template <int CIN, int COUT, bool RELU_IN, int SRC, int DST>
__global__ void __launch_bounds__(256)
gemm_kernel(const float* __restrict__ Xp, const float* __restrict__ W,
            const float* __restrict__ bin, int n)
{
    constexpr int CP = COUT / 16;  // cols per thread (4 or 2)
    __shared__ __align__(16) float Ws[CIN * COUT];
    __shared__ __align__(16) float bs[CIN];

    const float* __restrict__ X = (SRC == 0) ? Xp : (const float*)g_agg1;
    float* __restrict__ out =
        (DST == 0) ? g_xl1 : (DST == 1) ? g_xr1 : (DST == 2) ? g_xl2 : g_xr2;

    int tid = threadIdx.x;
    for (int i = tid; i < CIN * COUT; i += 256) Ws[i] = W[i];
    if (RELU_IN) {
        for (int i = tid; i < CIN; i += 256) bs[i] = bin[i];
    }
    __syncthreads();

    int tx = tid & 15;
    int ty = tid >> 4;
    int rbase = blockIdx.x * 64 + ty;

    float acc[4][CP];
#pragma unroll
    for (int r = 0; r < 4; r++)
#pragma unroll
        for (int c = 0; c < CP; c++) acc[r][c] = 0.f;

    int rows[4];
#pragma unroll
    for (int r = 0; r < 4; r++) {
        int row = rbase + 16 * r;
        rows[r] = row < n ? row : (n - 1);  // clamp: safe read, store guarded
    }

    for (int k = 0; k < CIN; k += 4) {
        float4 b4 = make_float4(0.f, 0.f, 0.f, 0.f);
        if (RELU_IN) b4 = *(const float4*)(bs + k);

        float xv[4][4];
#pragma unroll
        for (int r = 0; r < 4; r++) {
            float4 x4 = *(const float4*)(X + (size_t)rows[r] * CIN + k);
            if (RELU_IN) {
                x4.x = fmaxf(x4.x + b4.x, 0.f);
                x4.y = fmaxf(x4.y + b4.y, 0.f);
                x4.z = fmaxf(x4.z + b4.z, 0.f);
                x4.w = fmaxf(x4.w + b4.w, 0.f);
            }
            xv[r][0] = x4.x; xv[r][1] = x4.y; xv[r][2] = x4.z; xv[r][3] = x4.w;
        }

#pragma unroll
        for (int kk = 0; kk < 4; kk++) {
            float wv[CP];
            if constexpr (CP == 4) {
                float4 w4 = *(const float4*)(Ws + (k + kk) * COUT + tx * 4);
                wv[0] = w4.x; wv[1] = w4.y; wv[2] = w4.z; wv[3] = w4.w;
            } else {
                float2 w2 = *(const float2*)(Ws + (k + kk) * COUT + tx * 2);
                wv[0] = w2.x; wv[1] = w2.y;
            }
#pragma unroll
            for (int r = 0; r < 4; r++)
#pragma unroll
                for (int c = 0; c < CP; c++)
                    acc[r][c] = fmaf(xv[r][kk], wv[c], acc[r][c]);
        }
    }

#pragma unroll
    for (int r = 0; r < 4; r++) {
        int row = rbase + 16 * r;
        if (row < n) {
#pragma unroll
            for (int c = 0; c < CP; c++)
                out[(size_t)row * COUT + tx * CP + c] = acc[r][c];
        }
    }
}

// -------- layer 1 edge logits: 64ch, warp per edge ------------------
// logits = leakyrelu(xl[src] + xr[dst]) . att; expv = exp(logits);
// denom[dst] += expv  (no max-shift: logits are O(1), exp cannot overflow)
__global__ void edge_logits_l1(const int* __restrict__ ei,
                               const float* __restrict__ att, int nE)
{
    int lane = threadIdx.x & 31;
    int warp = (blockIdx.x * blockDim.x + threadIdx.x) >> 5;
    int nw = (gridDim.x * blockDim.x) >> 5;
    float2 av = ((const float2*)att)[lane];

    for (int e = warp; e < nE; e += nw) {
        int s = ei[e];
        int d = ei[nE + e];
        float2 a = ((const float2*)(g_xl1 + s * 64))[lane];
        float2 b = ((const float2*)(g_xr1 + d * 64))[lane];
        float ex = a.x + b.x, ey = a.y + b.y;
        ex = ex > 0.f ? ex : 0.2f * ex;
        ey = ey > 0.f ? ey : 0.2f * ey;
        float v = ex * av.x + ey * av.y;
#pragma unroll
        for (int o = 16; o > 0; o >>= 1) v += __shfl_xor_sync(0xffffffffu, v, o);
        if (lane == 0) {
            float evv = __expf(v);
            g_expv[e] = evv;
            atomicAdd(&g_den1[d], evv);
        }
    }
}

// -------- layer 1 aggregation: half-warp per edge -------------------
__global__ void edge_aggr_l1(const int* __restrict__ ei, int nE)
{
    int lane = threadIdx.x & 31;
    int warp = (blockIdx.x * blockDim.x + threadIdx.x) >> 5;
    int nw = (gridDim.x * blockDim.x) >> 5;
    int sub = lane >> 4;   // which of 2 edges
    int l = lane & 15;     // float4 slot: 16 * 4 = 64 channels

    for (int e0 = warp * 2; e0 < nE; e0 += nw * 2) {
        int e = e0 + sub;  // nE is even
        int s = ei[e];
        int d = ei[nE + e];
        float evv = g_expv[e];
        float den = g_den1[d];
        float alpha = evv / (den + 1e-16f);
        float4 xv = ((const float4*)(g_xl1 + s * 64))[l];
        float* base = g_agg1 + d * 64 + l * 4;
        atomicAdd(base + 0, alpha * xv.x);
        atomicAdd(base + 1, alpha * xv.y);
        atomicAdd(base + 2, alpha * xv.z);
        atomicAdd(base + 3, alpha * xv.w);
    }
}

// -------- layer 2 edge logits: 32ch, 2 edges per warp ---------------
__global__ void edge_logits_l2(const int* __restrict__ ei,
                               const float* __restrict__ att, int nE)
{
    int lane = threadIdx.x & 31;
    int warp = (blockIdx.x * blockDim.x + threadIdx.x) >> 5;
    int nw = (gridDim.x * blockDim.x) >> 5;
    int sub = lane >> 4;
    int l = lane & 15;
    float2 av = ((const float2*)att)[l];

    for (int e0 = warp * 2; e0 < nE; e0 += nw * 2) {
        int e = e0 + sub;
        int s = ei[e];
        int d = ei[nE + e];
        float2 a = ((const float2*)(g_xl2 + s * 32))[l];
        float2 b = ((const float2*)(g_xr2 + d * 32))[l];
        float ex = a.x + b.x, ey = a.y + b.y;
        ex = ex > 0.f ? ex : 0.2f * ex;
        ey = ey > 0.f ? ey : 0.2f * ey;
        float v = ex * av.x + ey * av.y;
#pragma unroll
        for (int o = 8; o > 0; o >>= 1) v += __shfl_xor_sync(0xffffffffu, v, o);
        if (l == 0) {
            float evv = __expf(v);
            g_expv[e] = evv;
            atomicAdd(&g_den2[d], evv);
        }
    }
}

// -------- layer 2 aggregation: 4 edges per warp ---------------------
__global__ void edge_aggr_l2(const int* __restrict__ ei, int nE)
{
    int lane = threadIdx.x & 31;
    int warp = (blockIdx.x * blockDim.x + threadIdx.x) >> 5;
    int nw = (gridDim.x * blockDim.x) >> 5;
    int sub = lane >> 3;   // 4 edges
    int l = lane & 7;      // 8 * 4 = 32 channels

    for (int e0 = warp * 4; e0 < nE; e0 += nw * 4) {
        int e = e0 + sub;  // nE divisible by 4
        int s = ei[e];
        int d = ei[nE + e];
        float evv = g_expv[e];
        float den = g_den2[d];
        float alpha = evv / (den + 1e-16f);
        float4 xv = ((const float4*)(g_xl2 + s * 32))[l];
        float* base = g_agg2 + d * 32 + l * 4;
        atomicAdd(base + 0, alpha * xv.x);
        atomicAdd(base + 1, alpha * xv.y);
        atomicAdd(base + 2, alpha * xv.z);
        atomicAdd(base + 3, alpha * xv.w);
    }
}

// -------- final: softplus(agg2 + b2) + 1e-6 -------------------------
__global__ void final_kernel(const float* __restrict__ b2, float* __restrict__ out, int n)
{
    int i = blockIdx.x * blockDim.x + threadIdx.x;
    int stride = gridDim.x * blockDim.x;
    for (int j = i; j < n * 32; j += stride) {
        float v = g_agg2[j] + b2[j & 31];
        float sp = fmaxf(v, 0.f) + log1pf(__expf(-fabsf(v)));
        out[j] = sp + 1e-6f;
    }
}

// ====================================================================
extern "C" void kernel_launch(void* const* d_in, const int* in_sizes, int n_in,
                              void* d_out, int out_size)
{
    const float* x    = (const float*)d_in[0];
    const int*   ei   = (const int*)d_in[1];    // int32 per harness dtype contract
    const float* W1l  = (const float*)d_in[2];
    const float* W1r  = (const float*)d_in[3];
    const float* att1 = (const float*)d_in[4];
    const float* b1   = (const float*)d_in[5];
    const float* W2l  = (const float*)d_in[6];
    const float* W2r  = (const float*)d_in[7];
    const float* att2 = (const float*)d_in[8];
    const float* b2   = (const float*)d_in[9];
    float*       out  = (float*)d_out;

    int n = in_sizes[0] / 128;   // 50000
    int E = in_sizes[1] / 2;     // 800000

    const int EDGE_BLOCKS = 2048;
    int gemm_blocks = (n + 63) / 64;

    zero_kernel<<<2048, 256>>>(n);

    gemm_kernel<128, 64, false, 0, 0><<<gemm_blocks, 256>>>(x, W1l, b1, n);
    gemm_kernel<128, 64, false, 0, 1><<<gemm_blocks, 256>>>(x, W1r, b1, n);

    edge_logits_l1<<<EDGE_BLOCKS, 256>>>(ei, att1, E);
    edge_aggr_l1<<<EDGE_BLOCKS, 256>>>(ei, E);

    // layer 2 input transform fused into GEMM load: relu(agg1 + b1)
    gemm_kernel<64, 32, true, 1, 2><<<gemm_blocks, 256>>>(x, W2l, b1, n);
    gemm_kernel<64, 32, true, 1, 3><<<gemm_blocks, 256>>>(x, W2r, b1, n);

    edge_logits_l2<<<EDGE_BLOCKS, 256>>>(ei, att2, E);
    edge_aggr_l2<<<EDGE_BLOCKS, 256>>>(ei, E);

    final_kernel<<<2048, 256>>>(b2, out, n);
}

// round 7
// speedup vs baseline: 1.4174x; 1.4174x over previous
#include <cuda_runtime.h>
#include <cuda_bf16.h>

// Problem constants (buffers statically sized; runtime sizes from in_sizes)
#define NMAX 50000
#define EMAX 800000

// -------- scratch (device globals; no allocations allowed) ----------
__device__ __align__(16) float g_xl1[NMAX * 64];
__device__ __align__(16) float g_xr1[NMAX * 64];
__device__ __align__(16) float g_agg1[NMAX * 64];
__device__ __align__(16) float g_xl2[NMAX * 32];
__device__ __align__(16) float g_xr2[NMAX * 32];
__device__ __align__(16) float g_agg2[NMAX * 32];

// CSR by destination node (built once, reused by both layers)
__device__ int g_deg[NMAX];
__device__ int g_off[NMAX + 1];
__device__ int g_pos[NMAX];
__device__ int g_csrc[EMAX];   // source node per CSR slot

// -------- CSR build -------------------------------------------------
__global__ void zerodeg_kernel(int n) {
    int i = blockIdx.x * blockDim.x + threadIdx.x;
    if (i < n) g_deg[i] = 0;
}

__global__ void count_kernel(const int* __restrict__ ei, int nE) {
    int i = blockIdx.x * blockDim.x + threadIdx.x;
    int stride = gridDim.x * blockDim.x;
    for (int e = i; e < nE; e += stride)
        atomicAdd(&g_deg[ei[nE + e]], 1);
}

// single-block exclusive scan of g_deg -> g_off (and g_pos copy)
__global__ void __launch_bounds__(1024) scan_kernel(int n, int nE) {
    __shared__ int warpsum[32];
    int t = threadIdx.x;
    int lane = t & 31;
    int wid = t >> 5;
    int per = (n + 1023) / 1024;
    int beg = t * per;
    int end = beg + per < n ? beg + per : n;

    int s = 0;
    for (int i = beg; i < end; i++) s += g_deg[i];

    // warp inclusive scan of chunk sums
    int incl = s;
#pragma unroll
    for (int o = 1; o < 32; o <<= 1) {
        int v = __shfl_up_sync(0xffffffffu, incl, o);
        if (lane >= o) incl += v;
    }
    if (lane == 31) warpsum[wid] = incl;
    __syncthreads();
    if (wid == 0) {
        int ws = warpsum[lane];
        int wincl = ws;
#pragma unroll
        for (int o = 1; o < 32; o <<= 1) {
            int v = __shfl_up_sync(0xffffffffu, wincl, o);
            if (lane >= o) wincl += v;
        }
        warpsum[lane] = wincl - ws;  // exclusive warp base
    }
    __syncthreads();

    int base = warpsum[wid] + (incl - s);  // exclusive prefix for this thread's chunk
    int run = base;
    for (int i = beg; i < end; i++) {
        g_off[i] = run;
        g_pos[i] = run;
        run += g_deg[i];
    }
    if (t == 0) g_off[n] = nE;
}

__global__ void fill_kernel(const int* __restrict__ ei, int nE) {
    int i = blockIdx.x * blockDim.x + threadIdx.x;
    int stride = gridDim.x * blockDim.x;
    for (int e = i; e < nE; e += stride) {
        int s = ei[e];
        int d = ei[nE + e];
        int p = atomicAdd(&g_pos[d], 1);
        g_csrc[p] = s;
    }
}

// -------- GEMM: out[n, COUT] = f(X)[n, CIN] @ W[CIN, COUT] ----------
// SRC: 0 = external X param, 1 = g_agg1.  DST: 0=g_xl1 1=g_xr1 2=g_xl2 3=g_xr2.
// f = identity, or relu(x + bin) when RELU_IN (layer-2 input transform).
template <int CIN, int COUT, bool RELU_IN, int SRC, int DST>
__global__ void __launch_bounds__(256)
gemm_kernel(const float* __restrict__ Xp, const float* __restrict__ W,
            const float* __restrict__ bin, int n)
{
    constexpr int CP = COUT / 16;  // cols per thread (4 or 2)
    __shared__ __align__(16) float Ws[CIN * COUT];
    __shared__ __align__(16) float bs[CIN];

    const float* __restrict__ X = (SRC == 0) ? Xp : (const float*)g_agg1;
    float* __restrict__ out =
        (DST == 0) ? g_xl1 : (DST == 1) ? g_xr1 : (DST == 2) ? g_xl2 : g_xr2;

    int tid = threadIdx.x;
    for (int i = tid; i < CIN * COUT; i += 256) Ws[i] = W[i];
    if (RELU_IN) {
        for (int i = tid; i < CIN; i += 256) bs[i] = bin[i];
    }
    __syncthreads();

    int tx = tid & 15;
    int ty = tid >> 4;
    int rbase = blockIdx.x * 64 + ty;

    float acc[4][CP];
#pragma unroll
    for (int r = 0; r < 4; r++)
#pragma unroll
        for (int c = 0; c < CP; c++) acc[r][c] = 0.f;

    int rows[4];
#pragma unroll
    for (int r = 0; r < 4; r++) {
        int row = rbase + 16 * r;
        rows[r] = row < n ? row : (n - 1);  // clamp: safe read, store guarded
    }

    for (int k = 0; k < CIN; k += 4) {
        float4 b4 = make_float4(0.f, 0.f, 0.f, 0.f);
        if (RELU_IN) b4 = *(const float4*)(bs + k);

        float xv[4][4];
#pragma unroll
        for (int r = 0; r < 4; r++) {
            float4 x4 = *(const float4*)(X + (size_t)rows[r] * CIN + k);
            if (RELU_IN) {
                x4.x = fmaxf(x4.x + b4.x, 0.f);
                x4.y = fmaxf(x4.y + b4.y, 0.f);
                x4.z = fmaxf(x4.z + b4.z, 0.f);
                x4.w = fmaxf(x4.w + b4.w, 0.f);
            }
            xv[r][0] = x4.x; xv[r][1] = x4.y; xv[r][2] = x4.z; xv[r][3] = x4.w;
        }

#pragma unroll
        for (int kk = 0; kk < 4; kk++) {
            float wv[CP];
            if constexpr (CP == 4) {
                float4 w4 = *(const float4*)(Ws + (k + kk) * COUT + tx * 4);
                wv[0] = w4.x; wv[1] = w4.y; wv[2] = w4.z; wv[3] = w4.w;
            } else {
                float2 w2 = *(const float2*)(Ws + (k + kk) * COUT + tx * 2);
                wv[0] = w2.x; wv[1] = w2.y;
            }
#pragma unroll
            for (int r = 0; r < 4; r++)
#pragma unroll
                for (int c = 0; c < CP; c++)
                    acc[r][c] = fmaf(xv[r][kk], wv[c], acc[r][c]);
        }
    }

#pragma unroll
    for (int r = 0; r < 4; r++) {
        int row = rbase + 16 * r;
        if (row < n) {
#pragma unroll
            for (int c = 0; c < CP; c++)
                out[(size_t)row * COUT + tx * CP + c] = acc[r][c];
        }
    }
}

// -------- layer 1 fused node kernel: warp per dst node --------------
// For node d: acc = sum_e exp(leaky(xl[s]+xr[d]).att) * xl[s]; den = sum exp
// out = acc/(den+1e-16).  64 channels: lane owns 2 (float2).
__global__ void node_layer1(const float* __restrict__ att, int n)
{
    int lane = threadIdx.x & 31;
    int warp = (blockIdx.x * blockDim.x + threadIdx.x) >> 5;
    int nw = (gridDim.x * blockDim.x) >> 5;
    float2 av = ((const float2*)att)[lane];

    for (int node = warp; node < n; node += nw) {
        int beg = g_off[node];
        int end = g_off[node + 1];
        float2 xr = ((const float2*)(g_xr1 + node * 64))[lane];
        float2 acc = make_float2(0.f, 0.f);
        float den = 0.f;

        int i = beg;
        for (; i + 1 < end; i += 2) {
            int s0 = g_csrc[i];
            int s1 = g_csrc[i + 1];
            float2 a0 = ((const float2*)(g_xl1 + s0 * 64))[lane];
            float2 a1 = ((const float2*)(g_xl1 + s1 * 64))[lane];
            float e0x = a0.x + xr.x, e0y = a0.y + xr.y;
            float e1x = a1.x + xr.x, e1y = a1.y + xr.y;
            e0x = e0x > 0.f ? e0x : 0.2f * e0x;
            e0y = e0y > 0.f ? e0y : 0.2f * e0y;
            e1x = e1x > 0.f ? e1x : 0.2f * e1x;
            e1y = e1y > 0.f ? e1y : 0.2f * e1y;
            float v0 = e0x * av.x + e0y * av.y;
            float v1 = e1x * av.x + e1y * av.y;
#pragma unroll
            for (int o = 16; o > 0; o >>= 1) {
                v0 += __shfl_xor_sync(0xffffffffu, v0, o);
                v1 += __shfl_xor_sync(0xffffffffu, v1, o);
            }
            float w0 = __expf(v0);
            float w1 = __expf(v1);
            acc.x += w0 * a0.x + w1 * a1.x;
            acc.y += w0 * a0.y + w1 * a1.y;
            den += w0 + w1;
        }
        if (i < end) {
            int s0 = g_csrc[i];
            float2 a0 = ((const float2*)(g_xl1 + s0 * 64))[lane];
            float e0x = a0.x + xr.x, e0y = a0.y + xr.y;
            e0x = e0x > 0.f ? e0x : 0.2f * e0x;
            e0y = e0y > 0.f ? e0y : 0.2f * e0y;
            float v0 = e0x * av.x + e0y * av.y;
#pragma unroll
            for (int o = 16; o > 0; o >>= 1)
                v0 += __shfl_xor_sync(0xffffffffu, v0, o);
            float w0 = __expf(v0);
            acc.x += w0 * a0.x;
            acc.y += w0 * a0.y;
            den += w0;
        }

        float inv = 1.f / (den + 1e-16f);
        ((float2*)(g_agg1 + node * 64))[lane] = make_float2(acc.x * inv, acc.y * inv);
    }
}

// -------- layer 2 fused node kernel: warp per dst node, 32 ch -------
__global__ void node_layer2(const float* __restrict__ att, int n)
{
    int lane = threadIdx.x & 31;
    int warp = (blockIdx.x * blockDim.x + threadIdx.x) >> 5;
    int nw = (gridDim.x * blockDim.x) >> 5;
    float av = att[lane];

    for (int node = warp; node < n; node += nw) {
        int beg = g_off[node];
        int end = g_off[node + 1];
        float xr = g_xr2[node * 32 + lane];
        float acc = 0.f;
        float den = 0.f;

        int i = beg;
        for (; i + 1 < end; i += 2) {
            int s0 = g_csrc[i];
            int s1 = g_csrc[i + 1];
            float a0 = g_xl2[s0 * 32 + lane];
            float a1 = g_xl2[s1 * 32 + lane];
            float e0 = a0 + xr, e1 = a1 + xr;
            e0 = e0 > 0.f ? e0 : 0.2f * e0;
            e1 = e1 > 0.f ? e1 : 0.2f * e1;
            float v0 = e0 * av;
            float v1 = e1 * av;
#pragma unroll
            for (int o = 16; o > 0; o >>= 1) {
                v0 += __shfl_xor_sync(0xffffffffu, v0, o);
                v1 += __shfl_xor_sync(0xffffffffu, v1, o);
            }
            float w0 = __expf(v0);
            float w1 = __expf(v1);
            acc += w0 * a0 + w1 * a1;
            den += w0 + w1;
        }
        if (i < end) {
            int s0 = g_csrc[i];
            float a0 = g_xl2[s0 * 32 + lane];
            float e0 = a0 + xr;
            e0 = e0 > 0.f ? e0 : 0.2f * e0;
            float v0 = e0 * av;
#pragma unroll
            for (int o = 16; o > 0; o >>= 1)
                v0 += __shfl_xor_sync(0xffffffffu, v0, o);
            float w0 = __expf(v0);
            acc += w0 * a0;
            den += w0;
        }

        float inv = 1.f / (den + 1e-16f);
        g_agg2[node * 32 + lane] = acc * inv;
    }
}

// -------- final: softplus(agg2 + b2) + 1e-6 -------------------------
__global__ void final_kernel(const float* __restrict__ b2, float* __restrict__ out, int n)
{
    int i = blockIdx.x * blockDim.x + threadIdx.x;
    int stride = gridDim.x * blockDim.x;
    for (int j = i; j < n * 32; j += stride) {
        float v = g_agg2[j] + b2[j & 31];
        float sp = fmaxf(v, 0.f) + log1pf(__expf(-fabsf(v)));
        out[j] = sp + 1e-6f;
    }
}

// ====================================================================
extern "C" void kernel_launch(void* const* d_in, const int* in_sizes, int n_in,
                              void* d_out, int out_size)
{
    const float* x    = (const float*)d_in[0];
    const int*   ei   = (const int*)d_in[1];    // int32 per harness dtype contract
    const float* W1l  = (const float*)d_in[2];
    const float* W1r  = (const float*)d_in[3];
    const float* att1 = (const float*)d_in[4];
    const float* b1   = (const float*)d_in[5];
    const float* W2l  = (const float*)d_in[6];
    const float* W2r  = (const float*)d_in[7];
    const float* att2 = (const float*)d_in[8];
    const float* b2   = (const float*)d_in[9];
    float*       out  = (float*)d_out;

    int n = in_sizes[0] / 128;   // 50000
    int E = in_sizes[1] / 2;     // 800000

    int gemm_blocks = (n + 63) / 64;
    int node_blocks = (n * 32 + 255) / 256;  // warp per node
    int edge_blocks = (E + 255) / 256;

    // CSR build (dst-indexed), reused by both layers
    zerodeg_kernel<<<(n + 255) / 256, 256>>>(n);
    count_kernel<<<edge_blocks, 256>>>(ei, E);
    scan_kernel<<<1, 1024>>>(n, E);
    fill_kernel<<<edge_blocks, 256>>>(ei, E);

    // layer 1
    gemm_kernel<128, 64, false, 0, 0><<<gemm_blocks, 256>>>(x, W1l, b1, n);
    gemm_kernel<128, 64, false, 0, 1><<<gemm_blocks, 256>>>(x, W1r, b1, n);
    node_layer1<<<node_blocks, 256>>>(att1, n);

    // layer 2 (input transform relu(agg1 + b1) fused into GEMM load)
    gemm_kernel<64, 32, true, 1, 2><<<gemm_blocks, 256>>>(x, W2l, b1, n);
    gemm_kernel<64, 32, true, 1, 3><<<gemm_blocks, 256>>>(x, W2r, b1, n);
    node_layer2<<<node_blocks, 256>>>(att2, n);

    final_kernel<<<2048, 256>>>(b2, out, n);
}

// round 10
// speedup vs baseline: 1.4467x; 1.0207x over previous
#include <cuda_runtime.h>
#include <cuda_bf16.h>

// GATv2 x2 fused pipeline — CSR node-centric, 4-edge unroll (resubmit r10)
// Problem constants (buffers statically sized; runtime sizes from in_sizes)
#define NMAX 50000
#define EMAX 800000

// -------- scratch (device globals; no allocations allowed) ----------
__device__ __align__(16) float g_xl1[NMAX * 64];
__device__ __align__(16) float g_xr1[NMAX * 64];
__device__ __align__(16) float g_agg1[NMAX * 64];   // holds h = relu(agg+b1)
__device__ __align__(16) float g_xl2[NMAX * 32];
__device__ __align__(16) float g_xr2[NMAX * 32];

// CSR by destination node (built once, reused by both layers)
__device__ int g_deg[NMAX];
__device__ int g_off[NMAX + 1];
__device__ int g_pos[NMAX];
__device__ int g_csrc[EMAX];   // source node per CSR slot

// -------- CSR build -------------------------------------------------
__global__ void zerodeg_kernel(int n) {
    int i = blockIdx.x * blockDim.x + threadIdx.x;
    if (i < n) g_deg[i] = 0;
}

__global__ void count_kernel(const int* __restrict__ ei, int nE) {
    int i = blockIdx.x * blockDim.x + threadIdx.x;
    int stride = gridDim.x * blockDim.x;
    for (int e = i; e < nE; e += stride)
        atomicAdd(&g_deg[ei[nE + e]], 1);
}

// single-block exclusive scan of g_deg -> g_off (and g_pos copy)
__global__ void __launch_bounds__(1024) scan_kernel(int n, int nE) {
    __shared__ int warpsum[32];
    int t = threadIdx.x;
    int lane = t & 31;
    int wid = t >> 5;
    int per = (n + 1023) / 1024;
    int beg = t * per;
    int end = beg + per < n ? beg + per : n;

    int s = 0;
    for (int i = beg; i < end; i++) s += g_deg[i];

    // warp inclusive scan of chunk sums
    int incl = s;
#pragma unroll
    for (int o = 1; o < 32; o <<= 1) {
        int v = __shfl_up_sync(0xffffffffu, incl, o);
        if (lane >= o) incl += v;
    }
    if (lane == 31) warpsum[wid] = incl;
    __syncthreads();
    if (wid == 0) {
        int ws = warpsum[lane];
        int wincl = ws;
#pragma unroll
        for (int o = 1; o < 32; o <<= 1) {
            int v = __shfl_up_sync(0xffffffffu, wincl, o);
            if (lane >= o) wincl += v;
        }
        warpsum[lane] = wincl - ws;  // exclusive warp base
    }
    __syncthreads();

    int base = warpsum[wid] + (incl - s);  // exclusive prefix for this thread's chunk
    int run = base;
    for (int i = beg; i < end; i++) {
        g_off[i] = run;
        g_pos[i] = run;
        run += g_deg[i];
    }
    if (t == 0) g_off[n] = nE;
}

__global__ void fill_kernel(const int* __restrict__ ei, int nE) {
    int i = blockIdx.x * blockDim.x + threadIdx.x;
    int stride = gridDim.x * blockDim.x;
    for (int e = i; e < nE; e += stride) {
        int s = ei[e];
        int d = ei[nE + e];
        int p = atomicAdd(&g_pos[d], 1);
        g_csrc[p] = s;
    }
}

// -------- GEMM: out[n, COUT] = X[n, CIN] @ W[CIN, COUT] -------------
// SRC: 0 = external X param, 1 = g_agg1.  DST: 0=g_xl1 1=g_xr1 2=g_xl2 3=g_xr2.
template <int CIN, int COUT, int SRC, int DST>
__global__ void __launch_bounds__(256)
gemm_kernel(const float* __restrict__ Xp, const float* __restrict__ W, int n)
{
    constexpr int CP = COUT / 16;  // cols per thread (4 or 2)
    __shared__ __align__(16) float Ws[CIN * COUT];

    const float* __restrict__ X = (SRC == 0) ? Xp : (const float*)g_agg1;
    float* __restrict__ out =
        (DST == 0) ? g_xl1 : (DST == 1) ? g_xr1 : (DST == 2) ? g_xl2 : g_xr2;

    int tid = threadIdx.x;
    for (int i = tid; i < CIN * COUT; i += 256) Ws[i] = W[i];
    __syncthreads();

    int tx = tid & 15;
    int ty = tid >> 4;
    int rbase = blockIdx.x * 64 + ty;

    float acc[4][CP];
#pragma unroll
    for (int r = 0; r < 4; r++)
#pragma unroll
        for (int c = 0; c < CP; c++) acc[r][c] = 0.f;

    int rows[4];
#pragma unroll
    for (int r = 0; r < 4; r++) {
        int row = rbase + 16 * r;
        rows[r] = row < n ? row : (n - 1);  // clamp: safe read, store guarded
    }

    for (int k = 0; k < CIN; k += 4) {
        float xv[4][4];
#pragma unroll
        for (int r = 0; r < 4; r++) {
            float4 x4 = *(const float4*)(X + (size_t)rows[r] * CIN + k);
            xv[r][0] = x4.x; xv[r][1] = x4.y; xv[r][2] = x4.z; xv[r][3] = x4.w;
        }

#pragma unroll
        for (int kk = 0; kk < 4; kk++) {
            float wv[CP];
            if constexpr (CP == 4) {
                float4 w4 = *(const float4*)(Ws + (k + kk) * COUT + tx * 4);
                wv[0] = w4.x; wv[1] = w4.y; wv[2] = w4.z; wv[3] = w4.w;
            } else {
                float2 w2 = *(const float2*)(Ws + (k + kk) * COUT + tx * 2);
                wv[0] = w2.x; wv[1] = w2.y;
            }
#pragma unroll
            for (int r = 0; r < 4; r++)
#pragma unroll
                for (int c = 0; c < CP; c++)
                    acc[r][c] = fmaf(xv[r][kk], wv[c], acc[r][c]);
        }
    }

#pragma unroll
    for (int r = 0; r < 4; r++) {
        int row = rbase + 16 * r;
        if (row < n) {
#pragma unroll
            for (int c = 0; c < CP; c++)
                out[(size_t)row * COUT + tx * CP + c] = acc[r][c];
        }
    }
}

// -------- layer 1 fused node kernel: warp per dst node --------------
// acc = sum_e exp(leaky(xl[s]+xr[d]).att) * xl[s]; den = sum exp
// store h = relu(acc/den + b1)   (feeds layer-2 GEMMs directly)
__global__ void node_layer1(const float* __restrict__ att,
                            const float* __restrict__ b1, int n)
{
    int lane = threadIdx.x & 31;
    int warp = (blockIdx.x * blockDim.x + threadIdx.x) >> 5;
    int nw = (gridDim.x * blockDim.x) >> 5;
    float2 av = ((const float2*)att)[lane];
    float2 bv = ((const float2*)b1)[lane];

    for (int node = warp; node < n; node += nw) {
        int beg = g_off[node];
        int end = g_off[node + 1];
        float2 xr = ((const float2*)(g_xr1 + node * 64))[lane];
        float2 acc = make_float2(0.f, 0.f);
        float den = 0.f;

        int i = beg;
        for (; i + 3 < end; i += 4) {
            int s0 = g_csrc[i];
            int s1 = g_csrc[i + 1];
            int s2 = g_csrc[i + 2];
            int s3 = g_csrc[i + 3];
            float2 a0 = ((const float2*)(g_xl1 + s0 * 64))[lane];
            float2 a1 = ((const float2*)(g_xl1 + s1 * 64))[lane];
            float2 a2 = ((const float2*)(g_xl1 + s2 * 64))[lane];
            float2 a3 = ((const float2*)(g_xl1 + s3 * 64))[lane];
            float e0x = a0.x + xr.x, e0y = a0.y + xr.y;
            float e1x = a1.x + xr.x, e1y = a1.y + xr.y;
            float e2x = a2.x + xr.x, e2y = a2.y + xr.y;
            float e3x = a3.x + xr.x, e3y = a3.y + xr.y;
            e0x = e0x > 0.f ? e0x : 0.2f * e0x;  e0y = e0y > 0.f ? e0y : 0.2f * e0y;
            e1x = e1x > 0.f ? e1x : 0.2f * e1x;  e1y = e1y > 0.f ? e1y : 0.2f * e1y;
            e2x = e2x > 0.f ? e2x : 0.2f * e2x;  e2y = e2y > 0.f ? e2y : 0.2f * e2y;
            e3x = e3x > 0.f ? e3x : 0.2f * e3x;  e3y = e3y > 0.f ? e3y : 0.2f * e3y;
            float v0 = e0x * av.x + e0y * av.y;
            float v1 = e1x * av.x + e1y * av.y;
            float v2 = e2x * av.x + e2y * av.y;
            float v3 = e3x * av.x + e3y * av.y;
#pragma unroll
            for (int o = 16; o > 0; o >>= 1) {
                v0 += __shfl_xor_sync(0xffffffffu, v0, o);
                v1 += __shfl_xor_sync(0xffffffffu, v1, o);
                v2 += __shfl_xor_sync(0xffffffffu, v2, o);
                v3 += __shfl_xor_sync(0xffffffffu, v3, o);
            }
            float w0 = __expf(v0);
            float w1 = __expf(v1);
            float w2 = __expf(v2);
            float w3 = __expf(v3);
            acc.x += w0 * a0.x + w1 * a1.x + w2 * a2.x + w3 * a3.x;
            acc.y += w0 * a0.y + w1 * a1.y + w2 * a2.y + w3 * a3.y;
            den += (w0 + w1) + (w2 + w3);
        }
        for (; i < end; i++) {
            int s0 = g_csrc[i];
            float2 a0 = ((const float2*)(g_xl1 + s0 * 64))[lane];
            float e0x = a0.x + xr.x, e0y = a0.y + xr.y;
            e0x = e0x > 0.f ? e0x : 0.2f * e0x;
            e0y = e0y > 0.f ? e0y : 0.2f * e0y;
            float v0 = e0x * av.x + e0y * av.y;
#pragma unroll
            for (int o = 16; o > 0; o >>= 1)
                v0 += __shfl_xor_sync(0xffffffffu, v0, o);
            float w0 = __expf(v0);
            acc.x += w0 * a0.x;
            acc.y += w0 * a0.y;
            den += w0;
        }

        float inv = 1.f / (den + 1e-16f);
        float hx = fmaxf(acc.x * inv + bv.x, 0.f);
        float hy = fmaxf(acc.y * inv + bv.y, 0.f);
        ((float2*)(g_agg1 + node * 64))[lane] = make_float2(hx, hy);
    }
}

// -------- layer 2 fused node kernel + softplus epilogue -------------
// out[node] = softplus(acc/den + b2) + 1e-6   (written straight to d_out)
__global__ void node_layer2(const float* __restrict__ att,
                            const float* __restrict__ b2,
                            float* __restrict__ out, int n)
{
    int lane = threadIdx.x & 31;
    int warp = (blockIdx.x * blockDim.x + threadIdx.x) >> 5;
    int nw = (gridDim.x * blockDim.x) >> 5;
    float av = att[lane];
    float bv = b2[lane];

    for (int node = warp; node < n; node += nw) {
        int beg = g_off[node];
        int end = g_off[node + 1];
        float xr = g_xr2[node * 32 + lane];
        float acc = 0.f;
        float den = 0.f;

        int i = beg;
        for (; i + 3 < end; i += 4) {
            int s0 = g_csrc[i];
            int s1 = g_csrc[i + 1];
            int s2 = g_csrc[i + 2];
            int s3 = g_csrc[i + 3];
            float a0 = g_xl2[s0 * 32 + lane];
            float a1 = g_xl2[s1 * 32 + lane];
            float a2 = g_xl2[s2 * 32 + lane];
            float a3 = g_xl2[s3 * 32 + lane];
            float e0 = a0 + xr, e1 = a1 + xr, e2 = a2 + xr, e3 = a3 + xr;
            e0 = e0 > 0.f ? e0 : 0.2f * e0;
            e1 = e1 > 0.f ? e1 : 0.2f * e1;
            e2 = e2 > 0.f ? e2 : 0.2f * e2;
            e3 = e3 > 0.f ? e3 : 0.2f * e3;
            float v0 = e0 * av, v1 = e1 * av, v2 = e2 * av, v3 = e3 * av;
#pragma unroll
            for (int o = 16; o > 0; o >>= 1) {
                v0 += __shfl_xor_sync(0xffffffffu, v0, o);
                v1 += __shfl_xor_sync(0xffffffffu, v1, o);
                v2 += __shfl_xor_sync(0xffffffffu, v2, o);
                v3 += __shfl_xor_sync(0xffffffffu, v3, o);
            }
            float w0 = __expf(v0);
            float w1 = __expf(v1);
            float w2 = __expf(v2);
            float w3 = __expf(v3);
            acc += w0 * a0 + w1 * a1 + w2 * a2 + w3 * a3;
            den += (w0 + w1) + (w2 + w3);
        }
        for (; i < end; i++) {
            int s0 = g_csrc[i];
            float a0 = g_xl2[s0 * 32 + lane];
            float e0 = a0 + xr;
            e0 = e0 > 0.f ? e0 : 0.2f * e0;
            float v0 = e0 * av;
#pragma unroll
            for (int o = 16; o > 0; o >>= 1)
                v0 += __shfl_xor_sync(0xffffffffu, v0, o);
            float w0 = __expf(v0);
            acc += w0 * a0;
            den += w0;
        }

        float v = acc / (den + 1e-16f) + bv;
        float sp = fmaxf(v, 0.f) + log1pf(__expf(-fabsf(v)));
        out[node * 32 + lane] = sp + 1e-6f;
    }
}

// ====================================================================
extern "C" void kernel_launch(void* const* d_in, const int* in_sizes, int n_in,
                              void* d_out, int out_size)
{
    const float* x    = (const float*)d_in[0];
    const int*   ei   = (const int*)d_in[1];    // int32 per harness dtype contract
    const float* W1l  = (const float*)d_in[2];
    const float* W1r  = (const float*)d_in[3];
    const float* att1 = (const float*)d_in[4];
    const float* b1   = (const float*)d_in[5];
    const float* W2l  = (const float*)d_in[6];
    const float* W2r  = (const float*)d_in[7];
    const float* att2 = (const float*)d_in[8];
    const float* b2   = (const float*)d_in[9];
    float*       out  = (float*)d_out;

    int n = in_sizes[0] / 128;   // 50000
    int E = in_sizes[1] / 2;     // 800000

    int gemm_blocks = (n + 63) / 64;
    int node_blocks = (n * 32 + 255) / 256;  // warp per node
    int edge_blocks = (E + 255) / 256;

    // CSR build (dst-indexed), reused by both layers
    zerodeg_kernel<<<(n + 255) / 256, 256>>>(n);
    count_kernel<<<edge_blocks, 256>>>(ei, E);
    scan_kernel<<<1, 1024>>>(n, E);
    fill_kernel<<<edge_blocks, 256>>>(ei, E);

    // layer 1
    gemm_kernel<128, 64, 0, 0><<<gemm_blocks, 256>>>(x, W1l, n);
    gemm_kernel<128, 64, 0, 1><<<gemm_blocks, 256>>>(x, W1r, n);
    node_layer1<<<node_blocks, 256>>>(att1, b1, n);   // stores h = relu(.+b1)

    // layer 2 (g_agg1 already holds h)
    gemm_kernel<64, 32, 1, 2><<<gemm_blocks, 256>>>(x, W2l, n);
    gemm_kernel<64, 32, 1, 3><<<gemm_blocks, 256>>>(x, W2r, n);
    node_layer2<<<node_blocks, 256>>>(att2, b2, out, n);  // fused softplus -> d_out
}

// round 11
// speedup vs baseline: 1.5344x; 1.0606x over previous
#include <cuda_runtime.h>
#include <cuda_bf16.h>

// GATv2 x2 fused pipeline — CSR node-centric, sub-warp-per-edge node kernels
#define NMAX 50000
#define EMAX 800000

// -------- scratch (device globals; no allocations allowed) ----------
__device__ __align__(16) float g_xl1[NMAX * 64];
__device__ __align__(16) float g_xr1[NMAX * 64];
__device__ __align__(16) float g_agg1[NMAX * 64];   // holds h = relu(agg+b1)
__device__ __align__(16) float g_xl2[NMAX * 32];
__device__ __align__(16) float g_xr2[NMAX * 32];

// CSR by destination node (built once, reused by both layers)
__device__ int g_deg[NMAX];
__device__ int g_off[NMAX + 1];
__device__ int g_pos[NMAX];
__device__ int g_csrc[EMAX];   // source node per CSR slot

// -------- CSR build -------------------------------------------------
__global__ void zerodeg_kernel(int n) {
    int i = blockIdx.x * blockDim.x + threadIdx.x;
    if (i < n) g_deg[i] = 0;
}

__global__ void count_kernel(const int* __restrict__ ei, int nE) {
    int i = blockIdx.x * blockDim.x + threadIdx.x;
    int stride = gridDim.x * blockDim.x;
    for (int e = i; e < nE; e += stride)
        atomicAdd(&g_deg[ei[nE + e]], 1);
}

// single-block exclusive scan of g_deg -> g_off (and g_pos copy)
__global__ void __launch_bounds__(1024) scan_kernel(int n, int nE) {
    __shared__ int warpsum[32];
    int t = threadIdx.x;
    int lane = t & 31;
    int wid = t >> 5;
    int per = (n + 1023) / 1024;
    int beg = t * per;
    int end = beg + per < n ? beg + per : n;

    int s = 0;
    for (int i = beg; i < end; i++) s += g_deg[i];

    int incl = s;
#pragma unroll
    for (int o = 1; o < 32; o <<= 1) {
        int v = __shfl_up_sync(0xffffffffu, incl, o);
        if (lane >= o) incl += v;
    }
    if (lane == 31) warpsum[wid] = incl;
    __syncthreads();
    if (wid == 0) {
        int ws = warpsum[lane];
        int wincl = ws;
#pragma unroll
        for (int o = 1; o < 32; o <<= 1) {
            int v = __shfl_up_sync(0xffffffffu, wincl, o);
            if (lane >= o) wincl += v;
        }
        warpsum[lane] = wincl - ws;  // exclusive warp base
    }
    __syncthreads();

    int base = warpsum[wid] + (incl - s);
    int run = base;
    for (int i = beg; i < end; i++) {
        g_off[i] = run;
        g_pos[i] = run;
        run += g_deg[i];
    }
    if (t == 0) g_off[n] = nE;
}

__global__ void fill_kernel(const int* __restrict__ ei, int nE) {
    int i = blockIdx.x * blockDim.x + threadIdx.x;
    int stride = gridDim.x * blockDim.x;
    for (int e = i; e < nE; e += stride) {
        int s = ei[e];
        int d = ei[nE + e];
        int p = atomicAdd(&g_pos[d], 1);
        g_csrc[p] = s;
    }
}

// -------- GEMM: out[n, COUT] = X[n, CIN] @ W[CIN, COUT] -------------
template <int CIN, int COUT, int SRC, int DST>
__global__ void __launch_bounds__(256)
gemm_kernel(const float* __restrict__ Xp, const float* __restrict__ W, int n)
{
    constexpr int CP = COUT / 16;
    __shared__ __align__(16) float Ws[CIN * COUT];

    const float* __restrict__ X = (SRC == 0) ? Xp : (const float*)g_agg1;
    float* __restrict__ out =
        (DST == 0) ? g_xl1 : (DST == 1) ? g_xr1 : (DST == 2) ? g_xl2 : g_xr2;

    int tid = threadIdx.x;
    for (int i = tid; i < CIN * COUT; i += 256) Ws[i] = W[i];
    __syncthreads();

    int tx = tid & 15;
    int ty = tid >> 4;
    int rbase = blockIdx.x * 64 + ty;

    float acc[4][CP];
#pragma unroll
    for (int r = 0; r < 4; r++)
#pragma unroll
        for (int c = 0; c < CP; c++) acc[r][c] = 0.f;

    int rows[4];
#pragma unroll
    for (int r = 0; r < 4; r++) {
        int row = rbase + 16 * r;
        rows[r] = row < n ? row : (n - 1);
    }

    for (int k = 0; k < CIN; k += 4) {
        float xv[4][4];
#pragma unroll
        for (int r = 0; r < 4; r++) {
            float4 x4 = *(const float4*)(X + (size_t)rows[r] * CIN + k);
            xv[r][0] = x4.x; xv[r][1] = x4.y; xv[r][2] = x4.z; xv[r][3] = x4.w;
        }

#pragma unroll
        for (int kk = 0; kk < 4; kk++) {
            float wv[CP];
            if constexpr (CP == 4) {
                float4 w4 = *(const float4*)(Ws + (k + kk) * COUT + tx * 4);
                wv[0] = w4.x; wv[1] = w4.y; wv[2] = w4.z; wv[3] = w4.w;
            } else {
                float2 w2 = *(const float2*)(Ws + (k + kk) * COUT + tx * 2);
                wv[0] = w2.x; wv[1] = w2.y;
            }
#pragma unroll
            for (int r = 0; r < 4; r++)
#pragma unroll
                for (int c = 0; c < CP; c++)
                    acc[r][c] = fmaf(xv[r][kk], wv[c], acc[r][c]);
        }
    }

#pragma unroll
    for (int r = 0; r < 4; r++) {
        int row = rbase + 16 * r;
        if (row < n) {
#pragma unroll
            for (int c = 0; c < CP; c++)
                out[(size_t)row * COUT + tx * CP + c] = acc[r][c];
        }
    }
}

__device__ __forceinline__ float leaky02(float v) {
    return fmaxf(v, 0.2f * v);
}

// -------- layer 1 node kernel: warp/node, half-warp/edge, float4 ----
// lane = half*16 + c; channel slot c covers ch 4c..4c+3.
__global__ void node_layer1(const float* __restrict__ att,
                            const float* __restrict__ b1, int n)
{
    int lane = threadIdx.x & 31;
    int warp = (blockIdx.x * blockDim.x + threadIdx.x) >> 5;
    int nw = (gridDim.x * blockDim.x) >> 5;
    int half = lane >> 4;
    int c = lane & 15;
    float4 av = ((const float4*)att)[c];
    float4 bv = ((const float4*)b1)[c];

    for (int node = warp; node < n; node += nw) {
        int beg = g_off[node];
        int end = g_off[node + 1];
        float4 xr = ((const float4*)(g_xr1 + node * 64))[c];
        float4 acc = make_float4(0.f, 0.f, 0.f, 0.f);
        float den = 0.f;

        int i = beg;
        // main: 4 edges per iteration (2 per half-warp)
        for (; i + 3 < end; i += 4) {
            int sA = g_csrc[i + half];
            int sB = g_csrc[i + 2 + half];
            float4 aA = ((const float4*)(g_xl1 + sA * 64))[c];
            float4 aB = ((const float4*)(g_xl1 + sB * 64))[c];
            float4 eA = make_float4(leaky02(aA.x + xr.x), leaky02(aA.y + xr.y),
                                    leaky02(aA.z + xr.z), leaky02(aA.w + xr.w));
            float4 eB = make_float4(leaky02(aB.x + xr.x), leaky02(aB.y + xr.y),
                                    leaky02(aB.z + xr.z), leaky02(aB.w + xr.w));
            float vA = eA.x * av.x + eA.y * av.y + eA.z * av.z + eA.w * av.w;
            float vB = eB.x * av.x + eB.y * av.y + eB.z * av.z + eB.w * av.w;
#pragma unroll
            for (int o = 8; o > 0; o >>= 1) {
                vA += __shfl_xor_sync(0xffffffffu, vA, o);
                vB += __shfl_xor_sync(0xffffffffu, vB, o);
            }
            float wA = __expf(vA);
            float wB = __expf(vB);
            acc.x += wA * aA.x + wB * aB.x;
            acc.y += wA * aA.y + wB * aB.y;
            acc.z += wA * aA.z + wB * aB.z;
            acc.w += wA * aA.w + wB * aB.w;
            den += wA + wB;
        }
        // tail: 2 edges per iteration, predicated
        for (; i < end; i += 2) {
            int e = i + half;
            bool valid = e < end;
            int s = g_csrc[valid ? e : (end - 1)];
            float4 a = ((const float4*)(g_xl1 + s * 64))[c];
            float4 ee = make_float4(leaky02(a.x + xr.x), leaky02(a.y + xr.y),
                                    leaky02(a.z + xr.z), leaky02(a.w + xr.w));
            float v = ee.x * av.x + ee.y * av.y + ee.z * av.z + ee.w * av.w;
#pragma unroll
            for (int o = 8; o > 0; o >>= 1)
                v += __shfl_xor_sync(0xffffffffu, v, o);
            float w = valid ? __expf(v) : 0.f;
            acc.x += w * a.x; acc.y += w * a.y;
            acc.z += w * a.z; acc.w += w * a.w;
            den += w;
        }

        // combine the two half-warps (disjoint edge subsets, same channels)
        acc.x += __shfl_xor_sync(0xffffffffu, acc.x, 16);
        acc.y += __shfl_xor_sync(0xffffffffu, acc.y, 16);
        acc.z += __shfl_xor_sync(0xffffffffu, acc.z, 16);
        acc.w += __shfl_xor_sync(0xffffffffu, acc.w, 16);
        den   += __shfl_xor_sync(0xffffffffu, den, 16);

        if (half == 0) {
            float inv = 1.f / (den + 1e-16f);
            float4 h;
            h.x = fmaxf(acc.x * inv + bv.x, 0.f);
            h.y = fmaxf(acc.y * inv + bv.y, 0.f);
            h.z = fmaxf(acc.z * inv + bv.z, 0.f);
            h.w = fmaxf(acc.w * inv + bv.w, 0.f);
            ((float4*)(g_agg1 + node * 64))[c] = h;
        }
    }
}

// -------- layer 2 node kernel: warp/node, quarter-warp/edge ---------
// lane = q*8 + c; channel slot c covers ch 4c..4c+3 (32 ch total).
__global__ void node_layer2(const float* __restrict__ att,
                            const float* __restrict__ b2,
                            float* __restrict__ out, int n)
{
    int lane = threadIdx.x & 31;
    int warp = (blockIdx.x * blockDim.x + threadIdx.x) >> 5;
    int nw = (gridDim.x * blockDim.x) >> 5;
    int q = lane >> 3;
    int c = lane & 7;
    float4 av = ((const float4*)att)[c];
    float4 bv = ((const float4*)b2)[c];

    for (int node = warp; node < n; node += nw) {
        int beg = g_off[node];
        int end = g_off[node + 1];
        float4 xr = ((const float4*)(g_xr2 + node * 32))[c];
        float4 acc = make_float4(0.f, 0.f, 0.f, 0.f);
        float den = 0.f;

        int i = beg;
        // main: 8 edges per iteration (2 per quarter-warp)
        for (; i + 7 < end; i += 8) {
            int sA = g_csrc[i + q];
            int sB = g_csrc[i + 4 + q];
            float4 aA = ((const float4*)(g_xl2 + sA * 32))[c];
            float4 aB = ((const float4*)(g_xl2 + sB * 32))[c];
            float4 eA = make_float4(leaky02(aA.x + xr.x), leaky02(aA.y + xr.y),
                                    leaky02(aA.z + xr.z), leaky02(aA.w + xr.w));
            float4 eB = make_float4(leaky02(aB.x + xr.x), leaky02(aB.y + xr.y),
                                    leaky02(aB.z + xr.z), leaky02(aB.w + xr.w));
            float vA = eA.x * av.x + eA.y * av.y + eA.z * av.z + eA.w * av.w;
            float vB = eB.x * av.x + eB.y * av.y + eB.z * av.z + eB.w * av.w;
#pragma unroll
            for (int o = 4; o > 0; o >>= 1) {
                vA += __shfl_xor_sync(0xffffffffu, vA, o);
                vB += __shfl_xor_sync(0xffffffffu, vB, o);
            }
            float wA = __expf(vA);
            float wB = __expf(vB);
            acc.x += wA * aA.x + wB * aB.x;
            acc.y += wA * aA.y + wB * aB.y;
            acc.z += wA * aA.z + wB * aB.z;
            acc.w += wA * aA.w + wB * aB.w;
            den += wA + wB;
        }
        // tail: 4 edges per iteration, predicated
        for (; i < end; i += 4) {
            int e = i + q;
            bool valid = e < end;
            int s = g_csrc[valid ? e : (end - 1)];
            float4 a = ((const float4*)(g_xl2 + s * 32))[c];
            float4 ee = make_float4(leaky02(a.x + xr.x), leaky02(a.y + xr.y),
                                    leaky02(a.z + xr.z), leaky02(a.w + xr.w));
            float v = ee.x * av.x + ee.y * av.y + ee.z * av.z + ee.w * av.w;
#pragma unroll
            for (int o = 4; o > 0; o >>= 1)
                v += __shfl_xor_sync(0xffffffffu, v, o);
            float w = valid ? __expf(v) : 0.f;
            acc.x += w * a.x; acc.y += w * a.y;
            acc.z += w * a.z; acc.w += w * a.w;
            den += w;
        }

        // combine the four quarter-warps
#pragma unroll
        for (int o = 8; o <= 16; o <<= 1) {
            acc.x += __shfl_xor_sync(0xffffffffu, acc.x, o);
            acc.y += __shfl_xor_sync(0xffffffffu, acc.y, o);
            acc.z += __shfl_xor_sync(0xffffffffu, acc.z, o);
            acc.w += __shfl_xor_sync(0xffffffffu, acc.w, o);
            den   += __shfl_xor_sync(0xffffffffu, den, o);
        }

        if (q == 0) {
            float inv = 1.f / (den + 1e-16f);
            float4 v4;
            v4.x = acc.x * inv + bv.x;
            v4.y = acc.y * inv + bv.y;
            v4.z = acc.z * inv + bv.z;
            v4.w = acc.w * inv + bv.w;
            float4 o4;
            o4.x = fmaxf(v4.x, 0.f) + log1pf(__expf(-fabsf(v4.x))) + 1e-6f;
            o4.y = fmaxf(v4.y, 0.f) + log1pf(__expf(-fabsf(v4.y))) + 1e-6f;
            o4.z = fmaxf(v4.z, 0.f) + log1pf(__expf(-fabsf(v4.z))) + 1e-6f;
            o4.w = fmaxf(v4.w, 0.f) + log1pf(__expf(-fabsf(v4.w))) + 1e-6f;
            ((float4*)(out + node * 32))[c] = o4;
        }
    }
}

// ====================================================================
extern "C" void kernel_launch(void* const* d_in, const int* in_sizes, int n_in,
                              void* d_out, int out_size)
{
    const float* x    = (const float*)d_in[0];
    const int*   ei   = (const int*)d_in[1];    // int32 per harness dtype contract
    const float* W1l  = (const float*)d_in[2];
    const float* W1r  = (const float*)d_in[3];
    const float* att1 = (const float*)d_in[4];
    const float* b1   = (const float*)d_in[5];
    const float* W2l  = (const float*)d_in[6];
    const float* W2r  = (const float*)d_in[7];
    const float* att2 = (const float*)d_in[8];
    const float* b2   = (const float*)d_in[9];
    float*       out  = (float*)d_out;

    int n = in_sizes[0] / 128;   // 50000
    int E = in_sizes[1] / 2;     // 800000

    int gemm_blocks = (n + 63) / 64;
    int node_blocks = (n * 32 + 255) / 256;  // warp per node
    int edge_blocks = (E + 255) / 256;

    // CSR build (dst-indexed), reused by both layers
    zerodeg_kernel<<<(n + 255) / 256, 256>>>(n);
    count_kernel<<<edge_blocks, 256>>>(ei, E);
    scan_kernel<<<1, 1024>>>(n, E);
    fill_kernel<<<edge_blocks, 256>>>(ei, E);

    // layer 1
    gemm_kernel<128, 64, 0, 0><<<gemm_blocks, 256>>>(x, W1l, n);
    gemm_kernel<128, 64, 0, 1><<<gemm_blocks, 256>>>(x, W1r, n);
    node_layer1<<<node_blocks, 256>>>(att1, b1, n);   // stores h = relu(.+b1)

    // layer 2 (g_agg1 already holds h)
    gemm_kernel<64, 32, 1, 2><<<gemm_blocks, 256>>>(x, W2l, n);
    gemm_kernel<64, 32, 1, 3><<<gemm_blocks, 256>>>(x, W2r, n);
    node_layer2<<<node_blocks, 256>>>(att2, b2, out, n);  // fused softplus -> d_out
}

// round 12
// speedup vs baseline: 2.4583x; 1.6021x over previous
#include <cuda_runtime.h>
#include <cuda_bf16.h>

// GATv2 x2 — CSR node-centric, parallel scan, fused l/r GEMM pairs
#define NMAX 50000
#define EMAX 800000

// -------- scratch (device globals; no allocations allowed) ----------
__device__ __align__(16) float g_xl1[NMAX * 64];
__device__ __align__(16) float g_xr1[NMAX * 64];
__device__ __align__(16) float g_agg1[NMAX * 64];   // holds h = relu(agg+b1)
__device__ __align__(16) float g_xl2[NMAX * 32];
__device__ __align__(16) float g_xr2[NMAX * 32];

// CSR by destination node (built once, reused by both layers)
__device__ int g_deg[NMAX];
__device__ int g_off[NMAX + 1];
__device__ int g_pos[NMAX];
__device__ int g_csrc[EMAX];
__device__ int g_bsum[256];

// -------- CSR build -------------------------------------------------
__global__ void zerodeg_kernel(int n) {
    int i = blockIdx.x * blockDim.x + threadIdx.x;
    if (i < n) g_deg[i] = 0;
}

__global__ void count_kernel(const int* __restrict__ ei, int nE) {
    int i = blockIdx.x * blockDim.x + threadIdx.x;
    int stride = gridDim.x * blockDim.x;
    for (int e = i; e < nE; e += stride)
        atomicAdd(&g_deg[ei[nE + e]], 1);
}

// phase A: per-block sums of g_deg chunks (grid = 256 blocks, 256 thr)
__global__ void scanA_kernel(int n) {
    __shared__ int sm[256];
    int b = blockIdx.x, t = threadIdx.x;
    int chunk = (n + 255) / 256;
    int i = b * chunk + t;
    int v = (t < chunk && i < n) ? g_deg[i] : 0;
    sm[t] = v;
    __syncthreads();
#pragma unroll
    for (int o = 128; o > 0; o >>= 1) {
        if (t < o) sm[t] += sm[t + o];
        __syncthreads();
    }
    if (t == 0) g_bsum[b] = sm[0];
}

// phase B: 1 block exclusive-scans the 256 block sums
__global__ void scanB_kernel(int n, int nE) {
    __shared__ int sm[256];
    int t = threadIdx.x;
    int v = g_bsum[t];
    sm[t] = v;
    __syncthreads();
#pragma unroll
    for (int o = 1; o < 256; o <<= 1) {
        int u = (t >= o) ? sm[t - o] : 0;
        __syncthreads();
        sm[t] += u;
        __syncthreads();
    }
    g_bsum[t] = sm[t] - v;   // exclusive prefix
    if (t == 0) g_off[n] = nE;
}

// phase C: local exclusive scan + base, write g_off / g_pos
__global__ void scanC_kernel(int n) {
    __shared__ int sm[256];
    int b = blockIdx.x, t = threadIdx.x;
    int chunk = (n + 255) / 256;
    int i = b * chunk + t;
    int v = (t < chunk && i < n) ? g_deg[i] : 0;
    sm[t] = v;
    __syncthreads();
#pragma unroll
    for (int o = 1; o < 256; o <<= 1) {
        int u = (t >= o) ? sm[t - o] : 0;
        __syncthreads();
        sm[t] += u;
        __syncthreads();
    }
    int off = g_bsum[b] + sm[t] - v;   // exclusive
    if (t < chunk && i < n) {
        g_off[i] = off;
        g_pos[i] = off;
    }
}

__global__ void fill_kernel(const int* __restrict__ ei, int nE) {
    int i = blockIdx.x * blockDim.x + threadIdx.x;
    int stride = gridDim.x * blockDim.x;
    for (int e = i; e < nE; e += stride) {
        int s = ei[e];
        int d = ei[nE + e];
        int p = atomicAdd(&g_pos[d], 1);
        g_csrc[p] = s;
    }
}

// -------- fused GEMM pair, layer 1: x[128] -> xl1[64], xr1[64] ------
// K chunked by 64 so Wl+Wr chunks fit in 32KB smem. X gathered once.
__global__ void __launch_bounds__(256)
gemm_pair1(const float* __restrict__ X, const float* __restrict__ Wla,
           const float* __restrict__ Wra, int n)
{
    __shared__ __align__(16) float Wl[64 * 64];
    __shared__ __align__(16) float Wr[64 * 64];

    int tid = threadIdx.x;
    int tx = tid & 15;          // 4 cols each (COUT=64)
    int ty = tid >> 4;
    int rbase = blockIdx.x * 64 + ty;

    float accl[4][4], accr[4][4];
#pragma unroll
    for (int r = 0; r < 4; r++)
#pragma unroll
        for (int c = 0; c < 4; c++) { accl[r][c] = 0.f; accr[r][c] = 0.f; }

    int rows[4];
#pragma unroll
    for (int r = 0; r < 4; r++) {
        int row = rbase + 16 * r;
        rows[r] = row < n ? row : (n - 1);
    }

    for (int kc = 0; kc < 128; kc += 64) {
        // load both 64x64 W chunks (contiguous rows kc..kc+63)
        const float4* sl = (const float4*)(Wla + kc * 64);
        const float4* sr = (const float4*)(Wra + kc * 64);
        for (int i = tid; i < 1024; i += 256) {
            ((float4*)Wl)[i] = sl[i];
            ((float4*)Wr)[i] = sr[i];
        }
        __syncthreads();

        for (int k = 0; k < 64; k += 4) {
            float xv[4][4];
#pragma unroll
            for (int r = 0; r < 4; r++) {
                float4 x4 = *(const float4*)(X + (size_t)rows[r] * 128 + kc + k);
                xv[r][0] = x4.x; xv[r][1] = x4.y; xv[r][2] = x4.z; xv[r][3] = x4.w;
            }
#pragma unroll
            for (int kk = 0; kk < 4; kk++) {
                float4 wl4 = *(const float4*)(Wl + (k + kk) * 64 + tx * 4);
                float4 wr4 = *(const float4*)(Wr + (k + kk) * 64 + tx * 4);
#pragma unroll
                for (int r = 0; r < 4; r++) {
                    float xs = xv[r][kk];
                    accl[r][0] = fmaf(xs, wl4.x, accl[r][0]);
                    accl[r][1] = fmaf(xs, wl4.y, accl[r][1]);
                    accl[r][2] = fmaf(xs, wl4.z, accl[r][2]);
                    accl[r][3] = fmaf(xs, wl4.w, accl[r][3]);
                    accr[r][0] = fmaf(xs, wr4.x, accr[r][0]);
                    accr[r][1] = fmaf(xs, wr4.y, accr[r][1]);
                    accr[r][2] = fmaf(xs, wr4.z, accr[r][2]);
                    accr[r][3] = fmaf(xs, wr4.w, accr[r][3]);
                }
            }
        }
        __syncthreads();
    }

#pragma unroll
    for (int r = 0; r < 4; r++) {
        int row = rbase + 16 * r;
        if (row < n) {
            float4 l4 = make_float4(accl[r][0], accl[r][1], accl[r][2], accl[r][3]);
            float4 r4 = make_float4(accr[r][0], accr[r][1], accr[r][2], accr[r][3]);
            *(float4*)(g_xl1 + (size_t)row * 64 + tx * 4) = l4;
            *(float4*)(g_xr1 + (size_t)row * 64 + tx * 4) = r4;
        }
    }
}

// -------- fused GEMM pair, layer 2: h[64] -> xl2[32], xr2[32] -------
__global__ void __launch_bounds__(256)
gemm_pair2(const float* __restrict__ Wla, const float* __restrict__ Wra, int n)
{
    __shared__ __align__(16) float Wl[64 * 32];
    __shared__ __align__(16) float Wr[64 * 32];
    const float* __restrict__ X = (const float*)g_agg1;

    int tid = threadIdx.x;
    int tx = tid & 15;          // 2 cols each (COUT=32)
    int ty = tid >> 4;
    int rbase = blockIdx.x * 64 + ty;

    for (int i = tid; i < 512; i += 256) {
        ((float4*)Wl)[i] = ((const float4*)Wla)[i];
        ((float4*)Wr)[i] = ((const float4*)Wra)[i];
    }
    __syncthreads();

    float accl[4][2], accr[4][2];
#pragma unroll
    for (int r = 0; r < 4; r++)
#pragma unroll
        for (int c = 0; c < 2; c++) { accl[r][c] = 0.f; accr[r][c] = 0.f; }

    int rows[4];
#pragma unroll
    for (int r = 0; r < 4; r++) {
        int row = rbase + 16 * r;
        rows[r] = row < n ? row : (n - 1);
    }

    for (int k = 0; k < 64; k += 4) {
        float xv[4][4];
#pragma unroll
        for (int r = 0; r < 4; r++) {
            float4 x4 = *(const float4*)(X + (size_t)rows[r] * 64 + k);
            xv[r][0] = x4.x; xv[r][1] = x4.y; xv[r][2] = x4.z; xv[r][3] = x4.w;
        }
#pragma unroll
        for (int kk = 0; kk < 4; kk++) {
            float2 wl2 = *(const float2*)(Wl + (k + kk) * 32 + tx * 2);
            float2 wr2 = *(const float2*)(Wr + (k + kk) * 32 + tx * 2);
#pragma unroll
            for (int r = 0; r < 4; r++) {
                float xs = xv[r][kk];
                accl[r][0] = fmaf(xs, wl2.x, accl[r][0]);
                accl[r][1] = fmaf(xs, wl2.y, accl[r][1]);
                accr[r][0] = fmaf(xs, wr2.x, accr[r][0]);
                accr[r][1] = fmaf(xs, wr2.y, accr[r][1]);
            }
        }
    }

#pragma unroll
    for (int r = 0; r < 4; r++) {
        int row = rbase + 16 * r;
        if (row < n) {
            *(float2*)(g_xl2 + (size_t)row * 32 + tx * 2) =
                make_float2(accl[r][0], accl[r][1]);
            *(float2*)(g_xr2 + (size_t)row * 32 + tx * 2) =
                make_float2(accr[r][0], accr[r][1]);
        }
    }
}

__device__ __forceinline__ float leaky02(float v) {
    return fmaxf(v, 0.2f * v);
}

// -------- layer 1 node kernel: warp/node, half-warp/edge, float4 ----
__global__ void node_layer1(const float* __restrict__ att,
                            const float* __restrict__ b1, int n)
{
    int lane = threadIdx.x & 31;
    int warp = (blockIdx.x * blockDim.x + threadIdx.x) >> 5;
    int nw = (gridDim.x * blockDim.x) >> 5;
    int half = lane >> 4;
    int c = lane & 15;
    float4 av = ((const float4*)att)[c];
    float4 bv = ((const float4*)b1)[c];

    for (int node = warp; node < n; node += nw) {
        int beg = g_off[node];
        int end = g_off[node + 1];
        float4 xr = ((const float4*)(g_xr1 + node * 64))[c];
        float4 acc = make_float4(0.f, 0.f, 0.f, 0.f);
        float den = 0.f;

        int i = beg;
        for (; i + 3 < end; i += 4) {
            int sA = g_csrc[i + half];
            int sB = g_csrc[i + 2 + half];
            float4 aA = ((const float4*)(g_xl1 + sA * 64))[c];
            float4 aB = ((const float4*)(g_xl1 + sB * 64))[c];
            float4 eA = make_float4(leaky02(aA.x + xr.x), leaky02(aA.y + xr.y),
                                    leaky02(aA.z + xr.z), leaky02(aA.w + xr.w));
            float4 eB = make_float4(leaky02(aB.x + xr.x), leaky02(aB.y + xr.y),
                                    leaky02(aB.z + xr.z), leaky02(aB.w + xr.w));
            float vA = eA.x * av.x + eA.y * av.y + eA.z * av.z + eA.w * av.w;
            float vB = eB.x * av.x + eB.y * av.y + eB.z * av.z + eB.w * av.w;
#pragma unroll
            for (int o = 8; o > 0; o >>= 1) {
                vA += __shfl_xor_sync(0xffffffffu, vA, o);
                vB += __shfl_xor_sync(0xffffffffu, vB, o);
            }
            float wA = __expf(vA);
            float wB = __expf(vB);
            acc.x += wA * aA.x + wB * aB.x;
            acc.y += wA * aA.y + wB * aB.y;
            acc.z += wA * aA.z + wB * aB.z;
            acc.w += wA * aA.w + wB * aB.w;
            den += wA + wB;
        }
        for (; i < end; i += 2) {
            int e = i + half;
            bool valid = e < end;
            int s = g_csrc[valid ? e : (end - 1)];
            float4 a = ((const float4*)(g_xl1 + s * 64))[c];
            float4 ee = make_float4(leaky02(a.x + xr.x), leaky02(a.y + xr.y),
                                    leaky02(a.z + xr.z), leaky02(a.w + xr.w));
            float v = ee.x * av.x + ee.y * av.y + ee.z * av.z + ee.w * av.w;
#pragma unroll
            for (int o = 8; o > 0; o >>= 1)
                v += __shfl_xor_sync(0xffffffffu, v, o);
            float w = valid ? __expf(v) : 0.f;
            acc.x += w * a.x; acc.y += w * a.y;
            acc.z += w * a.z; acc.w += w * a.w;
            den += w;
        }

        acc.x += __shfl_xor_sync(0xffffffffu, acc.x, 16);
        acc.y += __shfl_xor_sync(0xffffffffu, acc.y, 16);
        acc.z += __shfl_xor_sync(0xffffffffu, acc.z, 16);
        acc.w += __shfl_xor_sync(0xffffffffu, acc.w, 16);
        den   += __shfl_xor_sync(0xffffffffu, den, 16);

        if (half == 0) {
            float inv = 1.f / (den + 1e-16f);
            float4 h;
            h.x = fmaxf(acc.x * inv + bv.x, 0.f);
            h.y = fmaxf(acc.y * inv + bv.y, 0.f);
            h.z = fmaxf(acc.z * inv + bv.z, 0.f);
            h.w = fmaxf(acc.w * inv + bv.w, 0.f);
            ((float4*)(g_agg1 + node * 64))[c] = h;
        }
    }
}

// -------- layer 2 node kernel: warp/node, quarter-warp/edge ---------
__global__ void node_layer2(const float* __restrict__ att,
                            const float* __restrict__ b2,
                            float* __restrict__ out, int n)
{
    int lane = threadIdx.x & 31;
    int warp = (blockIdx.x * blockDim.x + threadIdx.x) >> 5;
    int nw = (gridDim.x * blockDim.x) >> 5;
    int q = lane >> 3;
    int c = lane & 7;
    float4 av = ((const float4*)att)[c];
    float4 bv = ((const float4*)b2)[c];

    for (int node = warp; node < n; node += nw) {
        int beg = g_off[node];
        int end = g_off[node + 1];
        float4 xr = ((const float4*)(g_xr2 + node * 32))[c];
        float4 acc = make_float4(0.f, 0.f, 0.f, 0.f);
        float den = 0.f;

        int i = beg;
        for (; i + 7 < end; i += 8) {
            int sA = g_csrc[i + q];
            int sB = g_csrc[i + 4 + q];
            float4 aA = ((const float4*)(g_xl2 + sA * 32))[c];
            float4 aB = ((const float4*)(g_xl2 + sB * 32))[c];
            float4 eA = make_float4(leaky02(aA.x + xr.x), leaky02(aA.y + xr.y),
                                    leaky02(aA.z + xr.z), leaky02(aA.w + xr.w));
            float4 eB = make_float4(leaky02(aB.x + xr.x), leaky02(aB.y + xr.y),
                                    leaky02(aB.z + xr.z), leaky02(aB.w + xr.w));
            float vA = eA.x * av.x + eA.y * av.y + eA.z * av.z + eA.w * av.w;
            float vB = eB.x * av.x + eB.y * av.y + eB.z * av.z + eB.w * av.w;
#pragma unroll
            for (int o = 4; o > 0; o >>= 1) {
                vA += __shfl_xor_sync(0xffffffffu, vA, o);
                vB += __shfl_xor_sync(0xffffffffu, vB, o);
            }
            float wA = __expf(vA);
            float wB = __expf(vB);
            acc.x += wA * aA.x + wB * aB.x;
            acc.y += wA * aA.y + wB * aB.y;
            acc.z += wA * aA.z + wB * aB.z;
            acc.w += wA * aA.w + wB * aB.w;
            den += wA + wB;
        }
        for (; i < end; i += 4) {
            int e = i + q;
            bool valid = e < end;
            int s = g_csrc[valid ? e : (end - 1)];
            float4 a = ((const float4*)(g_xl2 + s * 32))[c];
            float4 ee = make_float4(leaky02(a.x + xr.x), leaky02(a.y + xr.y),
                                    leaky02(a.z + xr.z), leaky02(a.w + xr.w));
            float v = ee.x * av.x + ee.y * av.y + ee.z * av.z + ee.w * av.w;
#pragma unroll
            for (int o = 4; o > 0; o >>= 1)
                v += __shfl_xor_sync(0xffffffffu, v, o);
            float w = valid ? __expf(v) : 0.f;
            acc.x += w * a.x; acc.y += w * a.y;
            acc.z += w * a.z; acc.w += w * a.w;
            den += w;
        }

#pragma unroll
        for (int o = 8; o <= 16; o <<= 1) {
            acc.x += __shfl_xor_sync(0xffffffffu, acc.x, o);
            acc.y += __shfl_xor_sync(0xffffffffu, acc.y, o);
            acc.z += __shfl_xor_sync(0xffffffffu, acc.z, o);
            acc.w += __shfl_xor_sync(0xffffffffu, acc.w, o);
            den   += __shfl_xor_sync(0xffffffffu, den, o);
        }

        if (q == 0) {
            float inv = 1.f / (den + 1e-16f);
            float4 v4;
            v4.x = acc.x * inv + bv.x;
            v4.y = acc.y * inv + bv.y;
            v4.z = acc.z * inv + bv.z;
            v4.w = acc.w * inv + bv.w;
            float4 o4;
            o4.x = fmaxf(v4.x, 0.f) + log1pf(__expf(-fabsf(v4.x))) + 1e-6f;
            o4.y = fmaxf(v4.y, 0.f) + log1pf(__expf(-fabsf(v4.y))) + 1e-6f;
            o4.z = fmaxf(v4.z, 0.f) + log1pf(__expf(-fabsf(v4.z))) + 1e-6f;
            o4.w = fmaxf(v4.w, 0.f) + log1pf(__expf(-fabsf(v4.w))) + 1e-6f;
            ((float4*)(out + node * 32))[c] = o4;
        }
    }
}

// ====================================================================
extern "C" void kernel_launch(void* const* d_in, const int* in_sizes, int n_in,
                              void* d_out, int out_size)
{
    const float* x    = (const float*)d_in[0];
    const int*   ei   = (const int*)d_in[1];    // int32 per harness dtype contract
    const float* W1l  = (const float*)d_in[2];
    const float* W1r  = (const float*)d_in[3];
    const float* att1 = (const float*)d_in[4];
    const float* b1   = (const float*)d_in[5];
    const float* W2l  = (const float*)d_in[6];
    const float* W2r  = (const float*)d_in[7];
    const float* att2 = (const float*)d_in[8];
    const float* b2   = (const float*)d_in[9];
    float*       out  = (float*)d_out;

    int n = in_sizes[0] / 128;   // 50000
    int E = in_sizes[1] / 2;     // 800000

    int gemm_blocks = (n + 63) / 64;
    int node_blocks = (n * 32 + 255) / 256;  // warp per node
    int edge_blocks = (E + 255) / 256;

    // CSR build (dst-indexed), reused by both layers
    zerodeg_kernel<<<(n + 255) / 256, 256>>>(n);
    count_kernel<<<edge_blocks, 256>>>(ei, E);
    scanA_kernel<<<256, 256>>>(n);
    scanB_kernel<<<1, 256>>>(n, E);
    scanC_kernel<<<256, 256>>>(n);
    fill_kernel<<<edge_blocks, 256>>>(ei, E);

    // layer 1
    gemm_pair1<<<gemm_blocks, 256>>>(x, W1l, W1r, n);
    node_layer1<<<node_blocks, 256>>>(att1, b1, n);   // stores h = relu(.+b1)

    // layer 2 (g_agg1 holds h)
    gemm_pair2<<<gemm_blocks, 256>>>(W2l, W2r, n);
    node_layer2<<<node_blocks, 256>>>(att2, b2, out, n);  // fused softplus -> d_out
}